// round 15
// baseline (speedup 1.0000x reference)
#include <cuda_runtime.h>
#include <cuda_fp16.h>
#include <cstdint>

// Problem constants (fixed by reference)
#define B_   8192   // batch
#define D_   256    // input dim
#define C_   512    // num centers
#define NORD 9      // order+1
#define F_   256    // output dim
#define KTOT (C_ * NORD)   // 4608

// ---------------- scratch (static device globals; no allocation) ----------
__device__ __align__(16) float g_dist[(size_t)B_ * C_];   // 16 MB
__device__ float g_x2[B_];
__device__ float g_c2[C_];
__device__ float g_bias_part[16][F_];
__device__ unsigned int g_minmax[2];
__device__ unsigned int g_bar;
// W packed in mma-fragment order, single fp16 (record = 16B uint4)
__device__ __align__(16) uint4 g_wf[2 * 32 * NORD * 8 * 32];   // 2.4 MB
// x packed in A-fragment order, single fp16: [mi(512)][kt(16)][lane(32)]
__device__ __align__(16) uint4 g_xf[(B_ / 16) * 16 * 32];      // 4 MB
// centers packed in B-fragment order, single fp16
__device__ __align__(16) uint4 g_cf[(C_ / 16) * 16 * 32];      // 256 KB

#define GRID_MAIN 128
#define CB_STRIDE (NORD * 8 * 512)   // 36864 bytes per chunk per fb-half

// ==================== small helpers ========================================
__device__ __forceinline__ void mma_fp16(float* d, const uint32_t* a,
                                         uint32_t b0, uint32_t b1) {
    asm volatile(
        "mma.sync.aligned.m16n8k16.row.col.f32.f16.f16.f32 "
        "{%0,%1,%2,%3}, {%4,%5,%6,%7}, {%8,%9}, {%0,%1,%2,%3};"
        : "+f"(d[0]), "+f"(d[1]), "+f"(d[2]), "+f"(d[3])
        : "r"(a[0]), "r"(a[1]), "r"(a[2]), "r"(a[3]), "r"(b0), "r"(b1));
}

__device__ __forceinline__ uint32_t pack_h(float v0, float v1) {
    __half2 h = __floats2half2_rn(v0, v1);
    return *(uint32_t*)&h;
}

// ---------------- fused prep kernel ----------------------------------------
#define NB_BIAS 16
#define NB_PX  (NB_BIAS + 1024)
#define NB_PC  (NB_PX + 64)
#define NB_PW  (NB_PC + 576)
#define NB_SQ  (NB_PW + 1088)
#define NB_ALL NB_SQ

__global__ void __launch_bounds__(256) k_prep_all(const float* __restrict__ x,
                                                  const float* __restrict__ cen,
                                                  const float* __restrict__ w) {
    const int b   = blockIdx.x;
    const int tid = threadIdx.x;

    if (b < NB_BIAS) {
        if (b == 0 && tid == 0) {
            g_minmax[0] = 0x7f800000u;
            g_minmax[1] = 0u;
            g_bar = 0u;
        }
        float s = 0.f;
        const float* wp = w + (size_t)(b * 32) * (NORD * F_) + tid;
        #pragma unroll
        for (int c = 0; c < 32; c++)
            s += wp[(size_t)c * (NORD * F_)];
        g_bias_part[b][tid] = s;
    } else if (b < NB_PX) {
        int gid  = (b - NB_BIAS) * 256 + tid;
        int lane = gid & 31;
        int kt   = (gid >> 5) & 15;
        int mi   = gid >> 9;
        int c0 = lane & 3, lr = lane >> 2;
        const float* px = x + (size_t)(mi * 16 + lr) * D_ + kt * 16 + 2 * c0;
        float2 v0 = *(const float2*)(px);
        float2 v1 = *(const float2*)(px + 8 * D_);
        float2 v2 = *(const float2*)(px + 8);
        float2 v3 = *(const float2*)(px + 8 * D_ + 8);
        g_xf[gid] = make_uint4(pack_h(v0.x, v0.y), pack_h(v1.x, v1.y),
                               pack_h(v2.x, v2.y), pack_h(v3.x, v3.y));
    } else if (b < NB_PC) {
        int gid  = (b - NB_PX) * 256 + tid;
        int lane = gid & 31;
        int kt   = (gid >> 5) & 15;
        int ni   = gid >> 9;
        int c0 = lane & 3, lr = lane >> 2;
        const float* pc = cen + (size_t)(ni * 16 + lr) * D_ + kt * 16 + 2 * c0;
        float2 v0 = *(const float2*)(pc);
        float2 v1 = *(const float2*)(pc + 8);
        float2 v2 = *(const float2*)(pc + 8 * D_);
        float2 v3 = *(const float2*)(pc + 8 * D_ + 8);
        g_cf[gid] = make_uint4(pack_h(v0.x, v0.y), pack_h(v1.x, v1.y),
                               pack_h(v2.x, v2.y), pack_h(v3.x, v3.y));
    } else if (b < NB_PW) {
        const int idx  = b - NB_PC;
        const int cb   = idx & 31;
        const int fb   = (idx >> 5) & 1;
        const int kt   = idx >> 6;
        const int lane = tid & 31;
        const int n16  = tid >> 5;
        const int c0   = lane & 3;
        const int fr   = lane >> 2;
        const int f0   = fb * 128 + n16 * 16 + fr;
        const int ci0  = cb * 16 + 2 * c0;
        float v[2][4];
        #pragma unroll
        for (int e = 0; e < 2; e++) {
            v[e][0] = w[((size_t)(ci0 + 0) * NORD + kt) * F_ + f0 + e * 8];
            v[e][1] = w[((size_t)(ci0 + 1) * NORD + kt) * F_ + f0 + e * 8];
            v[e][2] = w[((size_t)(ci0 + 8) * NORD + kt) * F_ + f0 + e * 8];
            v[e][3] = w[((size_t)(ci0 + 9) * NORD + kt) * F_ + f0 + e * 8];
        }
        g_wf[(((size_t)(fb * 32 + cb) * NORD + kt) * 8 + n16) * 32 + lane] =
            make_uint4(pack_h(v[0][0], v[0][1]), pack_h(v[0][2], v[0][3]),
                       pack_h(v[1][0], v[1][1]), pack_h(v[1][2], v[1][3]));
    } else {
        int warp = (b - NB_PW) * 8 + (tid >> 5);
        int lane = tid & 31;
        if (warp >= B_ + C_) return;
        const float* src;
        float* dst;
        if (warp < B_) { src = x   + (size_t)warp * D_;        dst = &g_x2[warp]; }
        else           { src = cen + (size_t)(warp - B_) * D_; dst = &g_c2[warp - B_]; }
        float s = 0.f;
        const float4* p = (const float4*)src;
        #pragma unroll
        for (int i = lane; i < D_ / 4; i += 32) {
            float4 v = p[i];
            s += v.x * v.x + v.y * v.y + v.z * v.z + v.w * v.w;
        }
        #pragma unroll
        for (int o = 16; o > 0; o >>= 1) s += __shfl_xor_sync(0xffffffffu, s, o);
        if (lane == 0) *dst = s;
    }
}

// ---------------- fused main kernel: dist phase + barrier + out phase ------
#define IDX(mt, r, c) (((mt) * 2 + (r)) * 4 + (c))

__global__ void __launch_bounds__(256, 1) k_main(float* __restrict__ out) {
    __shared__ unsigned int s_min, s_max;
    const int bx   = blockIdx.x;      // 0..127
    const int tid  = threadIdx.x;
    const int wid  = tid >> 5;
    const int lane = tid & 31;
    const int wm   = wid & 3;
    const int wn   = wid >> 2;
    const int tig  = lane & 3;
    const int lr   = lane >> 2;

    // ==================== phase 1: distance GEMM + min/max =================
    {
        const int n0 = (bx & 3) * 128;
        const int mp = bx >> 2;           // 0..31, two m-tiles each

        if (tid == 0) { s_min = 0x7f800000u; s_max = 0u; }

        float lmin = 3.4e38f, lmax = 0.f;

        for (int mb = 0; mb < 2; mb++) {
            const int m0 = (mp * 2 + mb) * 128;

            float acc[2][8][4];
            #pragma unroll
            for (int mt = 0; mt < 2; mt++)
                #pragma unroll
                for (int j = 0; j < 8; j++)
                    #pragma unroll
                    for (int e = 0; e < 4; e++) acc[mt][j][e] = 0.0f;

            const int mi0 = (m0 >> 4) + wm * 2;
            const int ni0 = (n0 >> 4) + wn * 4;

            #pragma unroll 4
            for (int kt = 0; kt < 16; kt++) {
                uint4 a[2], b[4];
                #pragma unroll
                for (int mt = 0; mt < 2; mt++)
                    a[mt] = g_xf[(size_t)((mi0 + mt) * 16 + kt) * 32 + lane];
                #pragma unroll
                for (int g = 0; g < 4; g++)
                    b[g] = g_cf[(size_t)((ni0 + g) * 16 + kt) * 32 + lane];
                #pragma unroll
                for (int g = 0; g < 4; g++)
                    #pragma unroll
                    for (int mt = 0; mt < 2; mt++) {
                        mma_fp16(acc[mt][g * 2 + 0], (const uint32_t*)&a[mt],
                                 b[g].x, b[g].y);
                        mma_fp16(acc[mt][g * 2 + 1], (const uint32_t*)&a[mt],
                                 b[g].z, b[g].w);
                    }
            }

            float x2r[2][2];
            #pragma unroll
            for (int mt = 0; mt < 2; mt++)
                #pragma unroll
                for (int rh = 0; rh < 2; rh++)
                    x2r[mt][rh] = g_x2[m0 + wm * 32 + mt * 16 + rh * 8 + lr];

            #pragma unroll
            for (int mt = 0; mt < 2; mt++) {
                #pragma unroll
                for (int j = 0; j < 8; j++) {
                    const int n = n0 + wn * 64 + j * 8 + tig * 2;
                    float2 c2v = *(const float2*)&g_c2[n];
                    #pragma unroll
                    for (int rh = 0; rh < 2; rh++) {
                        float xx = x2r[mt][rh];
                        float d0 = sqrtf(fmaxf(xx + c2v.x - 2.0f * acc[mt][j][rh * 2 + 0], 0.f));
                        float d1 = sqrtf(fmaxf(xx + c2v.y - 2.0f * acc[mt][j][rh * 2 + 1], 0.f));
                        lmin = fminf(lmin, fminf(d0, d1));
                        lmax = fmaxf(lmax, fmaxf(d0, d1));
                        const int row = m0 + wm * 32 + mt * 16 + rh * 8 + lr;
                        *(float2*)&g_dist[(size_t)row * C_ + n] = make_float2(d0, d1);
                    }
                }
            }
        }

        #pragma unroll
        for (int o = 16; o > 0; o >>= 1) {
            lmin = fminf(lmin, __shfl_xor_sync(0xffffffffu, lmin, o));
            lmax = fmaxf(lmax, __shfl_xor_sync(0xffffffffu, lmax, o));
        }
        __syncthreads();
        if (lane == 0) {
            atomicMin(&s_min, __float_as_uint(lmin));
            atomicMax(&s_max, __float_as_uint(lmax));
        }
        __syncthreads();
        if (tid == 0) {
            atomicMin(&g_minmax[0], s_min);
            atomicMax(&g_minmax[1], s_max);
        }
    }

    // ==================== grid barrier =====================================
    if (tid == 0) {
        __threadfence();
        atomicAdd(&g_bar, 1u);
        while (atomicAdd(&g_bar, 0u) < GRID_MAIN) __nanosleep(64);
    }
    __syncthreads();

    // ==================== phase 2: output fragment GEMM ====================
    {
        const int fb = bx & 1;
        const int m0 = (bx >> 1) * 128;
        const int f0 = fb * 128;
        const int c0 = tig;

        const float dmin  = __uint_as_float(g_minmax[0]);
        const float dmax  = __uint_as_float(g_minmax[1]);
        const float scale = 2.0f / (dmax - dmin);
        const float tc    = fmaf(-dmin, scale, -1.0f);

        const float* dp[4];
        #pragma unroll
        for (int q = 0; q < 4; q++) {
            int row = m0 + wm * 32 + (q >> 1) * 16 + (q & 1) * 8 + lr;
            dp[q] = g_dist + (size_t)row * C_ + 2 * c0;
        }

        // record = 16B; strides: g:512B, kt:4096B, cb:36864B
        const char* wfb = (const char*)g_wf
            + ((size_t)(fb * 32) * NORD * 8 + wn * 4) * 512 + lane * 16;

        // init accumulators with the exact P0 bias (sum of 16 partials)
        float acc[2][8][4];
        #pragma unroll
        for (int j = 0; j < 8; j++) {
            const int fz = f0 + wn * 64 + j * 8 + tig * 2;
            float2 bz = make_float2(0.f, 0.f);
            #pragma unroll
            for (int p = 0; p < 16; p++) {
                float2 v = *(const float2*)&g_bias_part[p][fz];
                bz.x += v.x;
                bz.y += v.y;
            }
            #pragma unroll
            for (int mt = 0; mt < 2; mt++) {
                acc[mt][j][0] = bz.x; acc[mt][j][1] = bz.y;
                acc[mt][j][2] = bz.x; acc[mt][j][3] = bz.y;
            }
        }

        float2 dv[8];
        #pragma unroll
        for (int q = 0; q < 4; q++) {
            dv[q * 2 + 0] = *(const float2*)(dp[q]);
            dv[q * 2 + 1] = *(const float2*)(dp[q] + 8);
        }

        // ---- continuous 1-deep B-fragment pipeline across kt and cb ----
        uint4 bc[4];
        #pragma unroll
        for (int g = 0; g < 4; g++)
            bc[g] = *(const uint4*)(wfb + 4096 + g * 512);   // cb=0, kt=1

        for (int cb = 0; cb < 32; cb++) {
            float t[16], pa[16], pb[16];
            #pragma unroll
            for (int q = 0; q < 4; q++) {
                t[q * 4 + 0] = fmaf(dv[q * 2 + 0].x, scale, tc);
                t[q * 4 + 1] = fmaf(dv[q * 2 + 0].y, scale, tc);
                t[q * 4 + 2] = fmaf(dv[q * 2 + 1].x, scale, tc);
                t[q * 4 + 3] = fmaf(dv[q * 2 + 1].y, scale, tc);
            }
            if (cb < 31) {
                #pragma unroll
                for (int q = 0; q < 4; q++) {
                    dv[q * 2 + 0] = *(const float2*)(dp[q] + (cb + 1) * 16);
                    dv[q * 2 + 1] = *(const float2*)(dp[q] + (cb + 1) * 16 + 8);
                }
            }
            #pragma unroll
            for (int i = 0; i < 16; i++) { pa[i] = 1.0f; pb[i] = t[i]; }

            const char* wpc = wfb + (size_t)cb * CB_STRIDE;

            #pragma unroll
            for (int kt = 1; kt < NORD; kt++) {
                // ---- prefetch next kt's B (or next chunk's kt=1) ----
                uint4 bn[4];
                {
                    const char* nxt = (kt < NORD - 1)
                        ? wpc + (size_t)(kt + 1) * 4096
                        : wpc + CB_STRIDE + 4096;   // next cb, kt=1
                    if (cb < 31 || kt < NORD - 1) {
                        #pragma unroll
                        for (int g = 0; g < 4; g++)
                            bn[g] = *(const uint4*)(nxt + g * 512);
                    }
                }

                // ---- A fragments for order kt (recurrence + pack) ----
                uint32_t ah[2][4];
                if (kt >= 2) {
                    const float an = (2.0f * kt - 1.0f) / (float)kt;
                    const float bn_ = (float)(kt - 1) / (float)kt;
                    #pragma unroll
                    for (int i = 0; i < 16; i++) {
                        float p2 = an * t[i] * pb[i] - bn_ * pa[i];
                        pa[i] = pb[i];
                        pb[i] = p2;
                    }
                }
                #pragma unroll
                for (int mt = 0; mt < 2; mt++) {
                    ah[mt][0] = pack_h(pb[IDX(mt,0,0)], pb[IDX(mt,0,1)]);
                    ah[mt][1] = pack_h(pb[IDX(mt,1,0)], pb[IDX(mt,1,1)]);
                    ah[mt][2] = pack_h(pb[IDX(mt,0,2)], pb[IDX(mt,0,3)]);
                    ah[mt][3] = pack_h(pb[IDX(mt,1,2)], pb[IDX(mt,1,3)]);
                }

                // ---- 16 independent mmas with current B ----
                #pragma unroll
                for (int g = 0; g < 4; g++)
                    #pragma unroll
                    for (int mt = 0; mt < 2; mt++) {
                        mma_fp16(acc[mt][g * 2 + 0], ah[mt], bc[g].x, bc[g].y);
                        mma_fp16(acc[mt][g * 2 + 1], ah[mt], bc[g].z, bc[g].w);
                    }

                #pragma unroll
                for (int g = 0; g < 4; g++) bc[g] = bn[g];
            }
        }

        // epilogue
        const int g = lr;
        #pragma unroll
        for (int mt = 0; mt < 2; mt++) {
            const int mb = m0 + wm * 32 + mt * 16;
            #pragma unroll
            for (int j = 0; j < 8; j++) {
                const int f = f0 + wn * 64 + j * 8 + tig * 2;
                float2 lo = make_float2(acc[mt][j][0], acc[mt][j][1]);
                float2 hi = make_float2(acc[mt][j][2], acc[mt][j][3]);
                *(float2*)(out + (size_t)(mb + g)     * F_ + f) = lo;
                *(float2*)(out + (size_t)(mb + g + 8) * F_ + f) = hi;
            }
        }
    }
}

// ---------------- launch ---------------------------------------------------
extern "C" void kernel_launch(void* const* d_in, const int* in_sizes, int n_in,
                              void* d_out, int out_size) {
    const float* x   = (const float*)d_in[0];   // [8192,256]
    const float* cen = (const float*)d_in[1];   // [512,256]
    const float* w   = (const float*)d_in[2];   // [512,9,256]
    float* out = (float*)d_out;                 // [8192,256]

    k_prep_all<<<NB_ALL, 256>>>(x, cen, w);
    k_main<<<GRID_MAIN, 256>>>(out);
}

// round 16
// speedup vs baseline: 1.0076x; 1.0076x over previous
#include <cuda_runtime.h>
#include <cuda_fp16.h>
#include <cstdint>

// Problem constants (fixed by reference)
#define B_   8192   // batch
#define D_   256    // input dim
#define C_   512    // num centers
#define NORD 9      // order+1
#define F_   256    // output dim
#define KTOT (C_ * NORD)   // 4608

// ---------------- scratch (static device globals; no allocation) ----------
__device__ __align__(16) float g_dist[(size_t)B_ * C_];   // 16 MB
__device__ float g_x2[B_];
__device__ float g_c2[C_];
__device__ float g_bias_part[16][F_];
__device__ unsigned int g_minmax[2];
__device__ volatile unsigned int g_bar;
// W packed in mma-fragment order, single fp16 (record = 16B uint4)
__device__ __align__(16) uint4 g_wf[2 * 32 * NORD * 8 * 32];   // 2.4 MB
// x packed in A-fragment order, single fp16: [mi(512)][kt(16)][lane(32)]
__device__ __align__(16) uint4 g_xf[(B_ / 16) * 16 * 32];      // 4 MB
// centers packed in B-fragment order, single fp16
__device__ __align__(16) uint4 g_cf[(C_ / 16) * 16 * 32];      // 256 KB

#define GRID_MAIN 128

// ==================== small helpers ========================================
__device__ __forceinline__ void mma_fp16(float* d, const uint32_t* a,
                                         uint32_t b0, uint32_t b1) {
    asm volatile(
        "mma.sync.aligned.m16n8k16.row.col.f32.f16.f16.f32 "
        "{%0,%1,%2,%3}, {%4,%5,%6,%7}, {%8,%9}, {%0,%1,%2,%3};"
        : "+f"(d[0]), "+f"(d[1]), "+f"(d[2]), "+f"(d[3])
        : "r"(a[0]), "r"(a[1]), "r"(a[2]), "r"(a[3]), "r"(b0), "r"(b1));
}

__device__ __forceinline__ uint32_t pack_h(float v0, float v1) {
    __half2 h = __floats2half2_rn(v0, v1);
    return *(uint32_t*)&h;
}

// ---------------- fused prep kernel ----------------------------------------
#define NB_BIAS 16
#define NB_PX  (NB_BIAS + 1024)
#define NB_PC  (NB_PX + 64)
#define NB_PW  (NB_PC + 576)
#define NB_SQ  (NB_PW + 1088)
#define NB_ALL NB_SQ

__global__ void __launch_bounds__(256) k_prep_all(const float* __restrict__ x,
                                                  const float* __restrict__ cen,
                                                  const float* __restrict__ w) {
    const int b   = blockIdx.x;
    const int tid = threadIdx.x;

    if (b < NB_BIAS) {
        if (b == 0 && tid == 0) {
            g_minmax[0] = 0x7f800000u;
            g_minmax[1] = 0u;
            g_bar = 0u;
        }
        float s = 0.f;
        const float* wp = w + (size_t)(b * 32) * (NORD * F_) + tid;
        #pragma unroll
        for (int c = 0; c < 32; c++)
            s += wp[(size_t)c * (NORD * F_)];
        g_bias_part[b][tid] = s;
    } else if (b < NB_PX) {
        int gid  = (b - NB_BIAS) * 256 + tid;
        int lane = gid & 31;
        int kt   = (gid >> 5) & 15;
        int mi   = gid >> 9;
        int c0 = lane & 3, lr = lane >> 2;
        const float* px = x + (size_t)(mi * 16 + lr) * D_ + kt * 16 + 2 * c0;
        float2 v0 = *(const float2*)(px);
        float2 v1 = *(const float2*)(px + 8 * D_);
        float2 v2 = *(const float2*)(px + 8);
        float2 v3 = *(const float2*)(px + 8 * D_ + 8);
        g_xf[gid] = make_uint4(pack_h(v0.x, v0.y), pack_h(v1.x, v1.y),
                               pack_h(v2.x, v2.y), pack_h(v3.x, v3.y));
    } else if (b < NB_PC) {
        int gid  = (b - NB_PX) * 256 + tid;
        int lane = gid & 31;
        int kt   = (gid >> 5) & 15;
        int ni   = gid >> 9;
        int c0 = lane & 3, lr = lane >> 2;
        const float* pc = cen + (size_t)(ni * 16 + lr) * D_ + kt * 16 + 2 * c0;
        float2 v0 = *(const float2*)(pc);
        float2 v1 = *(const float2*)(pc + 8);
        float2 v2 = *(const float2*)(pc + 8 * D_);
        float2 v3 = *(const float2*)(pc + 8 * D_ + 8);
        g_cf[gid] = make_uint4(pack_h(v0.x, v0.y), pack_h(v1.x, v1.y),
                               pack_h(v2.x, v2.y), pack_h(v3.x, v3.y));
    } else if (b < NB_PW) {
        const int idx  = b - NB_PC;
        const int cb   = idx & 31;
        const int fb   = (idx >> 5) & 1;
        const int kt   = idx >> 6;
        const int lane = tid & 31;
        const int n16  = tid >> 5;
        const int c0   = lane & 3;
        const int fr   = lane >> 2;
        const int f0   = fb * 128 + n16 * 16 + fr;
        const int ci0  = cb * 16 + 2 * c0;
        float v[2][4];
        #pragma unroll
        for (int e = 0; e < 2; e++) {
            v[e][0] = w[((size_t)(ci0 + 0) * NORD + kt) * F_ + f0 + e * 8];
            v[e][1] = w[((size_t)(ci0 + 1) * NORD + kt) * F_ + f0 + e * 8];
            v[e][2] = w[((size_t)(ci0 + 8) * NORD + kt) * F_ + f0 + e * 8];
            v[e][3] = w[((size_t)(ci0 + 9) * NORD + kt) * F_ + f0 + e * 8];
        }
        g_wf[(((size_t)(fb * 32 + cb) * NORD + kt) * 8 + n16) * 32 + lane] =
            make_uint4(pack_h(v[0][0], v[0][1]), pack_h(v[0][2], v[0][3]),
                       pack_h(v[1][0], v[1][1]), pack_h(v[1][2], v[1][3]));
    } else {
        int warp = (b - NB_PW) * 8 + (tid >> 5);
        int lane = tid & 31;
        if (warp >= B_ + C_) return;
        const float* src;
        float* dst;
        if (warp < B_) { src = x   + (size_t)warp * D_;        dst = &g_x2[warp]; }
        else           { src = cen + (size_t)(warp - B_) * D_; dst = &g_c2[warp - B_]; }
        float s = 0.f;
        const float4* p = (const float4*)src;
        #pragma unroll
        for (int i = lane; i < D_ / 4; i += 32) {
            float4 v = p[i];
            s += v.x * v.x + v.y * v.y + v.z * v.z + v.w * v.w;
        }
        #pragma unroll
        for (int o = 16; o > 0; o >>= 1) s += __shfl_xor_sync(0xffffffffu, s, o);
        if (lane == 0) *dst = s;
    }
}

// ---------------- fused main kernel: dist phase + barrier + out phase ------
#define IDX(mt, r, c) (((mt) * 2 + (r)) * 4 + (c))

__global__ void __launch_bounds__(256, 1) k_main(float* __restrict__ out) {
    __shared__ unsigned int s_min, s_max;
    const int bx   = blockIdx.x;      // 0..127
    const int tid  = threadIdx.x;
    const int wid  = tid >> 5;
    const int lane = tid & 31;
    const int wm   = wid & 3;
    const int wn   = wid >> 2;
    const int tig  = lane & 3;
    const int lr   = lane >> 2;

    // ==================== phase 1: distance GEMM + min/max =================
    {
        const int n0 = (bx & 3) * 128;
        const int mp = bx >> 2;           // 0..31, two m-tiles each

        if (tid == 0) { s_min = 0x7f800000u; s_max = 0u; }

        float lmin = 3.4e38f, lmax = 0.f;

        for (int mb = 0; mb < 2; mb++) {
            const int m0 = (mp * 2 + mb) * 128;

            float acc[2][8][4];
            #pragma unroll
            for (int mt = 0; mt < 2; mt++)
                #pragma unroll
                for (int j = 0; j < 8; j++)
                    #pragma unroll
                    for (int e = 0; e < 4; e++) acc[mt][j][e] = 0.0f;

            const int mi0 = (m0 >> 4) + wm * 2;
            const int ni0 = (n0 >> 4) + wn * 4;

            #pragma unroll 2
            for (int kt = 0; kt < 16; kt++) {
                uint4 a[2], b[4];
                #pragma unroll
                for (int mt = 0; mt < 2; mt++)
                    a[mt] = g_xf[(size_t)((mi0 + mt) * 16 + kt) * 32 + lane];
                #pragma unroll
                for (int g = 0; g < 4; g++)
                    b[g] = g_cf[(size_t)((ni0 + g) * 16 + kt) * 32 + lane];
                #pragma unroll
                for (int g = 0; g < 4; g++)
                    #pragma unroll
                    for (int mt = 0; mt < 2; mt++) {
                        mma_fp16(acc[mt][g * 2 + 0], (const uint32_t*)&a[mt],
                                 b[g].x, b[g].y);
                        mma_fp16(acc[mt][g * 2 + 1], (const uint32_t*)&a[mt],
                                 b[g].z, b[g].w);
                    }
            }

            float x2r[2][2];
            #pragma unroll
            for (int mt = 0; mt < 2; mt++)
                #pragma unroll
                for (int rh = 0; rh < 2; rh++)
                    x2r[mt][rh] = g_x2[m0 + wm * 32 + mt * 16 + rh * 8 + lr];

            #pragma unroll
            for (int mt = 0; mt < 2; mt++) {
                #pragma unroll
                for (int j = 0; j < 8; j++) {
                    const int n = n0 + wn * 64 + j * 8 + tig * 2;
                    float2 c2v = *(const float2*)&g_c2[n];
                    #pragma unroll
                    for (int rh = 0; rh < 2; rh++) {
                        float xx = x2r[mt][rh];
                        float d0 = sqrtf(fmaxf(xx + c2v.x - 2.0f * acc[mt][j][rh * 2 + 0], 0.f));
                        float d1 = sqrtf(fmaxf(xx + c2v.y - 2.0f * acc[mt][j][rh * 2 + 1], 0.f));
                        lmin = fminf(lmin, fminf(d0, d1));
                        lmax = fmaxf(lmax, fmaxf(d0, d1));
                        const int row = m0 + wm * 32 + mt * 16 + rh * 8 + lr;
                        *(float2*)&g_dist[(size_t)row * C_ + n] = make_float2(d0, d1);
                    }
                }
            }
        }

        #pragma unroll
        for (int o = 16; o > 0; o >>= 1) {
            lmin = fminf(lmin, __shfl_xor_sync(0xffffffffu, lmin, o));
            lmax = fmaxf(lmax, __shfl_xor_sync(0xffffffffu, lmax, o));
        }
        __syncthreads();
        if (lane == 0) {
            atomicMin(&s_min, __float_as_uint(lmin));
            atomicMax(&s_max, __float_as_uint(lmax));
        }
        __syncthreads();
        if (tid == 0) {
            atomicMin(&g_minmax[0], s_min);
            atomicMax(&g_minmax[1], s_max);
        }
    }

    // ==================== grid barrier =====================================
    if (tid == 0) {
        __threadfence();
        atomicAdd((unsigned int*)&g_bar, 1u);
        while (g_bar < GRID_MAIN) __nanosleep(128);
    }
    __syncthreads();

    // ==================== phase 2: output fragment GEMM ====================
    {
        const int fb = bx & 1;
        const int m0 = (bx >> 1) * 128;
        const int f0 = fb * 128;
        const int c0 = tig;

        const float dmin  = __uint_as_float(g_minmax[0]);
        const float dmax  = __uint_as_float(g_minmax[1]);
        const float scale = 2.0f / (dmax - dmin);
        const float tc    = fmaf(-dmin, scale, -1.0f);

        const float* dp[4];
        #pragma unroll
        for (int q = 0; q < 4; q++) {
            int row = m0 + wm * 32 + (q >> 1) * 16 + (q & 1) * 8 + lr;
            dp[q] = g_dist + (size_t)row * C_ + 2 * c0;
        }

        // record = 16B; strides: g:512B, kt:4096B, cb:36864B
        const char* wfb = (const char*)g_wf
            + ((size_t)(fb * 32) * NORD * 8 + wn * 4) * 512 + lane * 16;

        // init accumulators with the exact P0 bias (sum of 16 partials)
        float acc[2][8][4];
        #pragma unroll
        for (int j = 0; j < 8; j++) {
            const int fz = f0 + wn * 64 + j * 8 + tig * 2;
            float2 bz = make_float2(0.f, 0.f);
            #pragma unroll
            for (int p = 0; p < 16; p++) {
                float2 v = *(const float2*)&g_bias_part[p][fz];
                bz.x += v.x;
                bz.y += v.y;
            }
            #pragma unroll
            for (int mt = 0; mt < 2; mt++) {
                acc[mt][j][0] = bz.x; acc[mt][j][1] = bz.y;
                acc[mt][j][2] = bz.x; acc[mt][j][3] = bz.y;
            }
        }

        float2 dv[8];
        #pragma unroll
        for (int q = 0; q < 4; q++) {
            dv[q * 2 + 0] = *(const float2*)(dp[q]);
            dv[q * 2 + 1] = *(const float2*)(dp[q] + 8);
        }

        for (int cb = 0; cb < 32; cb++) {
            float t[16], pa[16], pb[16];
            #pragma unroll
            for (int q = 0; q < 4; q++) {
                t[q * 4 + 0] = fmaf(dv[q * 2 + 0].x, scale, tc);
                t[q * 4 + 1] = fmaf(dv[q * 2 + 0].y, scale, tc);
                t[q * 4 + 2] = fmaf(dv[q * 2 + 1].x, scale, tc);
                t[q * 4 + 3] = fmaf(dv[q * 2 + 1].y, scale, tc);
            }
            if (cb < 31) {
                #pragma unroll
                for (int q = 0; q < 4; q++) {
                    dv[q * 2 + 0] = *(const float2*)(dp[q] + (cb + 1) * 16);
                    dv[q * 2 + 1] = *(const float2*)(dp[q] + (cb + 1) * 16 + 8);
                }
            }
            #pragma unroll
            for (int i = 0; i < 16; i++) { pa[i] = 1.0f; pb[i] = t[i]; }

            const char* wpc = wfb + (size_t)cb * (NORD * 8 * 512);

            #pragma unroll
            for (int kt = 1; kt < NORD; kt++) {
                const char* wpt = wpc + (size_t)kt * 4096;
                uint4 b[4];
                #pragma unroll
                for (int g = 0; g < 4; g++)
                    b[g] = *(const uint4*)(wpt + g * 512);

                uint32_t ah[2][4];
                if (kt >= 2) {
                    const float an = (2.0f * kt - 1.0f) / (float)kt;
                    const float bn = (float)(kt - 1) / (float)kt;
                    #pragma unroll
                    for (int i = 0; i < 16; i++) {
                        float p2 = an * t[i] * pb[i] - bn * pa[i];
                        pa[i] = pb[i];
                        pb[i] = p2;
                    }
                }
                #pragma unroll
                for (int mt = 0; mt < 2; mt++) {
                    ah[mt][0] = pack_h(pb[IDX(mt,0,0)], pb[IDX(mt,0,1)]);
                    ah[mt][1] = pack_h(pb[IDX(mt,1,0)], pb[IDX(mt,1,1)]);
                    ah[mt][2] = pack_h(pb[IDX(mt,0,2)], pb[IDX(mt,0,3)]);
                    ah[mt][3] = pack_h(pb[IDX(mt,1,2)], pb[IDX(mt,1,3)]);
                }

                #pragma unroll
                for (int g = 0; g < 4; g++)
                    #pragma unroll
                    for (int mt = 0; mt < 2; mt++) {
                        mma_fp16(acc[mt][g * 2 + 0], ah[mt], b[g].x, b[g].y);
                        mma_fp16(acc[mt][g * 2 + 1], ah[mt], b[g].z, b[g].w);
                    }
            }
        }

        // epilogue
        const int g = lr;
        #pragma unroll
        for (int mt = 0; mt < 2; mt++) {
            const int mb = m0 + wm * 32 + mt * 16;
            #pragma unroll
            for (int j = 0; j < 8; j++) {
                const int f = f0 + wn * 64 + j * 8 + tig * 2;
                float2 lo = make_float2(acc[mt][j][0], acc[mt][j][1]);
                float2 hi = make_float2(acc[mt][j][2], acc[mt][j][3]);
                *(float2*)(out + (size_t)(mb + g)     * F_ + f) = lo;
                *(float2*)(out + (size_t)(mb + g + 8) * F_ + f) = hi;
            }
        }
    }
}

// ---------------- launch ---------------------------------------------------
extern "C" void kernel_launch(void* const* d_in, const int* in_sizes, int n_in,
                              void* d_out, int out_size) {
    const float* x   = (const float*)d_in[0];   // [8192,256]
    const float* cen = (const float*)d_in[1];   // [512,256]
    const float* w   = (const float*)d_in[2];   // [512,9,256]
    float* out = (float*)d_out;                 // [8192,256]

    k_prep_all<<<NB_ALL, 256>>>(x, cen, w);
    k_main<<<GRID_MAIN, 256>>>(out);
}

// round 17
// speedup vs baseline: 1.0542x; 1.0462x over previous
#include <cuda_runtime.h>
#include <cuda_fp16.h>
#include <cstdint>

// Problem constants (fixed by reference)
#define B_   8192   // batch
#define D_   256    // input dim
#define C_   512    // num centers
#define NORD 9      // order+1
#define F_   256    // output dim
#define KTOT (C_ * NORD)   // 4608

// ---------------- scratch (static device globals; no allocation) ----------
__device__ __align__(16) float g_dist[(size_t)B_ * C_];   // 16 MB
__device__ float g_x2[B_];                // accumulated via atomics; zeroed at
                                          // end of k_main for the next launch
__device__ float g_c2[C_];
__device__ float g_bias_part[16][F_];
__device__ unsigned int g_minmax[2];
__device__ unsigned int g_bar;
// W packed in mma-fragment order, single fp16 (record = 16B uint4)
__device__ __align__(16) uint4 g_wf[2 * 32 * NORD * 8 * 32];   // 2.4 MB
// x packed in A-fragment order, single fp16: [mi(512)][kt(16)][lane(32)]
__device__ __align__(16) uint4 g_xf[(B_ / 16) * 16 * 32];      // 4 MB
// centers packed in B-fragment order, single fp16
__device__ __align__(16) uint4 g_cf[(C_ / 16) * 16 * 32];      // 256 KB

#define GRID_MAIN 128

// ==================== small helpers ========================================
__device__ __forceinline__ void mma_fp16(float* d, const uint32_t* a,
                                         uint32_t b0, uint32_t b1) {
    asm volatile(
        "mma.sync.aligned.m16n8k16.row.col.f32.f16.f16.f32 "
        "{%0,%1,%2,%3}, {%4,%5,%6,%7}, {%8,%9}, {%0,%1,%2,%3};"
        : "+f"(d[0]), "+f"(d[1]), "+f"(d[2]), "+f"(d[3])
        : "r"(a[0]), "r"(a[1]), "r"(a[2]), "r"(a[3]), "r"(b0), "r"(b1));
}

__device__ __forceinline__ uint32_t pack_h(float v0, float v1) {
    __half2 h = __floats2half2_rn(v0, v1);
    return *(uint32_t*)&h;
}

// ---------------- fused prep kernel ----------------------------------------
// Block ranges:
//   [0, 16)        : P0-bias partial sums + minmax/bar init
//   [16, +1024)    : pack x (fp16 fragments) + fused x row-norm partials
//   [.., +64)      : pack centers
//   [.., +576)     : pack W
//   [.., +64)      : centers row norms
#define NB_BIAS 16
#define NB_PX  (NB_BIAS + 1024)
#define NB_PC  (NB_PX + 64)
#define NB_PW  (NB_PC + 576)
#define NB_SQC (NB_PW + 64)
#define NB_ALL NB_SQC

__global__ void __launch_bounds__(256) k_prep_all(const float* __restrict__ x,
                                                  const float* __restrict__ cen,
                                                  const float* __restrict__ w) {
    const int b   = blockIdx.x;
    const int tid = threadIdx.x;

    if (b < NB_BIAS) {
        if (b == 0 && tid == 0) {
            g_minmax[0] = 0x7f800000u;
            g_minmax[1] = 0u;
            g_bar = 0u;
        }
        float s = 0.f;
        const float* wp = w + (size_t)(b * 32) * (NORD * F_) + tid;
        #pragma unroll
        for (int c = 0; c < 32; c++)
            s += wp[(size_t)c * (NORD * F_)];
        g_bias_part[b][tid] = s;
    } else if (b < NB_PX) {
        // ---- pack x + fused squared-norm partials ----
        int gid  = (b - NB_BIAS) * 256 + tid;
        int lane = gid & 31;
        int kt   = (gid >> 5) & 15;
        int mi   = gid >> 9;
        int c0 = lane & 3, lr = lane >> 2;
        const float* px = x + (size_t)(mi * 16 + lr) * D_ + kt * 16 + 2 * c0;
        float2 v0 = *(const float2*)(px);
        float2 v1 = *(const float2*)(px + 8 * D_);
        float2 v2 = *(const float2*)(px + 8);
        float2 v3 = *(const float2*)(px + 8 * D_ + 8);
        g_xf[gid] = make_uint4(pack_h(v0.x, v0.y), pack_h(v1.x, v1.y),
                               pack_h(v2.x, v2.y), pack_h(v3.x, v3.y));
        // row-norm partials over this kt's 16 columns
        float s0 = v0.x * v0.x + v0.y * v0.y + v2.x * v2.x + v2.y * v2.y;
        float s1 = v1.x * v1.x + v1.y * v1.y + v3.x * v3.x + v3.y * v3.y;
        s0 += __shfl_xor_sync(0xffffffffu, s0, 1);
        s0 += __shfl_xor_sync(0xffffffffu, s0, 2);
        s1 += __shfl_xor_sync(0xffffffffu, s1, 1);
        s1 += __shfl_xor_sync(0xffffffffu, s1, 2);
        if (c0 == 0) {
            atomicAdd(&g_x2[mi * 16 + lr],     s0);
            atomicAdd(&g_x2[mi * 16 + lr + 8], s1);
        }
    } else if (b < NB_PC) {
        int gid  = (b - NB_PX) * 256 + tid;
        int lane = gid & 31;
        int kt   = (gid >> 5) & 15;
        int ni   = gid >> 9;
        int c0 = lane & 3, lr = lane >> 2;
        const float* pc = cen + (size_t)(ni * 16 + lr) * D_ + kt * 16 + 2 * c0;
        float2 v0 = *(const float2*)(pc);
        float2 v1 = *(const float2*)(pc + 8);
        float2 v2 = *(const float2*)(pc + 8 * D_);
        float2 v3 = *(const float2*)(pc + 8 * D_ + 8);
        g_cf[gid] = make_uint4(pack_h(v0.x, v0.y), pack_h(v1.x, v1.y),
                               pack_h(v2.x, v2.y), pack_h(v3.x, v3.y));
    } else if (b < NB_PW) {
        const int idx  = b - NB_PC;
        const int cb   = idx & 31;
        const int fb   = (idx >> 5) & 1;
        const int kt   = idx >> 6;
        const int lane = tid & 31;
        const int n16  = tid >> 5;
        const int c0   = lane & 3;
        const int fr   = lane >> 2;
        const int f0   = fb * 128 + n16 * 16 + fr;
        const int ci0  = cb * 16 + 2 * c0;
        float v[2][4];
        #pragma unroll
        for (int e = 0; e < 2; e++) {
            v[e][0] = w[((size_t)(ci0 + 0) * NORD + kt) * F_ + f0 + e * 8];
            v[e][1] = w[((size_t)(ci0 + 1) * NORD + kt) * F_ + f0 + e * 8];
            v[e][2] = w[((size_t)(ci0 + 8) * NORD + kt) * F_ + f0 + e * 8];
            v[e][3] = w[((size_t)(ci0 + 9) * NORD + kt) * F_ + f0 + e * 8];
        }
        g_wf[(((size_t)(fb * 32 + cb) * NORD + kt) * 8 + n16) * 32 + lane] =
            make_uint4(pack_h(v[0][0], v[0][1]), pack_h(v[0][2], v[0][3]),
                       pack_h(v[1][0], v[1][1]), pack_h(v[1][2], v[1][3]));
    } else {
        // ---- centers row norms (512 rows, one warp per row) ----
        int row  = (b - NB_PW) * 8 + (tid >> 5);
        int lane = tid & 31;
        if (row >= C_) return;
        float s = 0.f;
        const float4* p = (const float4*)(cen + (size_t)row * D_);
        #pragma unroll
        for (int i = lane; i < D_ / 4; i += 32) {
            float4 v = p[i];
            s += v.x * v.x + v.y * v.y + v.z * v.z + v.w * v.w;
        }
        #pragma unroll
        for (int o = 16; o > 0; o >>= 1) s += __shfl_xor_sync(0xffffffffu, s, o);
        if (lane == 0) g_c2[row] = s;
    }
}

// ---------------- fused main kernel: dist phase + barrier + out phase ------
#define IDX(mt, r, c) (((mt) * 2 + (r)) * 4 + (c))

__global__ void __launch_bounds__(256, 1) k_main(float* __restrict__ out) {
    __shared__ unsigned int s_min, s_max;
    const int bx   = blockIdx.x;      // 0..127
    const int tid  = threadIdx.x;
    const int wid  = tid >> 5;
    const int lane = tid & 31;
    const int wm   = wid & 3;
    const int wn   = wid >> 2;
    const int tig  = lane & 3;
    const int lr   = lane >> 2;

    // ==================== phase 1: distance GEMM + min/max =================
    {
        const int n0 = (bx & 3) * 128;
        const int mp = bx >> 2;           // 0..31, two m-tiles each

        if (tid == 0) { s_min = 0x7f800000u; s_max = 0u; }

        float lmin = 3.4e38f, lmax = 0.f;

        for (int mb = 0; mb < 2; mb++) {
            const int m0 = (mp * 2 + mb) * 128;

            float acc[2][8][4];
            #pragma unroll
            for (int mt = 0; mt < 2; mt++)
                #pragma unroll
                for (int j = 0; j < 8; j++)
                    #pragma unroll
                    for (int e = 0; e < 4; e++) acc[mt][j][e] = 0.0f;

            const int mi0 = (m0 >> 4) + wm * 2;
            const int ni0 = (n0 >> 4) + wn * 4;

            #pragma unroll 4
            for (int kt = 0; kt < 16; kt++) {
                uint4 a[2], b[4];
                #pragma unroll
                for (int mt = 0; mt < 2; mt++)
                    a[mt] = g_xf[(size_t)((mi0 + mt) * 16 + kt) * 32 + lane];
                #pragma unroll
                for (int g = 0; g < 4; g++)
                    b[g] = g_cf[(size_t)((ni0 + g) * 16 + kt) * 32 + lane];
                #pragma unroll
                for (int g = 0; g < 4; g++)
                    #pragma unroll
                    for (int mt = 0; mt < 2; mt++) {
                        mma_fp16(acc[mt][g * 2 + 0], (const uint32_t*)&a[mt],
                                 b[g].x, b[g].y);
                        mma_fp16(acc[mt][g * 2 + 1], (const uint32_t*)&a[mt],
                                 b[g].z, b[g].w);
                    }
            }

            float x2r[2][2];
            #pragma unroll
            for (int mt = 0; mt < 2; mt++)
                #pragma unroll
                for (int rh = 0; rh < 2; rh++)
                    x2r[mt][rh] = g_x2[m0 + wm * 32 + mt * 16 + rh * 8 + lr];

            #pragma unroll
            for (int mt = 0; mt < 2; mt++) {
                #pragma unroll
                for (int j = 0; j < 8; j++) {
                    const int n = n0 + wn * 64 + j * 8 + tig * 2;
                    float2 c2v = *(const float2*)&g_c2[n];
                    #pragma unroll
                    for (int rh = 0; rh < 2; rh++) {
                        float xx = x2r[mt][rh];
                        float d0 = sqrtf(fmaxf(xx + c2v.x - 2.0f * acc[mt][j][rh * 2 + 0], 0.f));
                        float d1 = sqrtf(fmaxf(xx + c2v.y - 2.0f * acc[mt][j][rh * 2 + 1], 0.f));
                        lmin = fminf(lmin, fminf(d0, d1));
                        lmax = fmaxf(lmax, fmaxf(d0, d1));
                        const int row = m0 + wm * 32 + mt * 16 + rh * 8 + lr;
                        *(float2*)&g_dist[(size_t)row * C_ + n] = make_float2(d0, d1);
                    }
                }
            }
        }

        #pragma unroll
        for (int o = 16; o > 0; o >>= 1) {
            lmin = fminf(lmin, __shfl_xor_sync(0xffffffffu, lmin, o));
            lmax = fmaxf(lmax, __shfl_xor_sync(0xffffffffu, lmax, o));
        }
        __syncthreads();
        if (lane == 0) {
            atomicMin(&s_min, __float_as_uint(lmin));
            atomicMax(&s_max, __float_as_uint(lmax));
        }
        __syncthreads();
        if (tid == 0) {
            atomicMin(&g_minmax[0], s_min);
            atomicMax(&g_minmax[1], s_max);
        }
    }

    // ==================== grid barrier =====================================
    if (tid == 0) {
        __threadfence();
        atomicAdd(&g_bar, 1u);
        while (atomicAdd(&g_bar, 0u) < GRID_MAIN) __nanosleep(64);
    }
    __syncthreads();

    // ==================== phase 2: output fragment GEMM ====================
    {
        const int fb = bx & 1;
        const int m0 = (bx >> 1) * 128;
        const int f0 = fb * 128;
        const int c0 = tig;

        const float dmin  = __uint_as_float(g_minmax[0]);
        const float dmax  = __uint_as_float(g_minmax[1]);
        const float scale = 2.0f / (dmax - dmin);
        const float tc    = fmaf(-dmin, scale, -1.0f);

        const float* dp[4];
        #pragma unroll
        for (int q = 0; q < 4; q++) {
            int row = m0 + wm * 32 + (q >> 1) * 16 + (q & 1) * 8 + lr;
            dp[q] = g_dist + (size_t)row * C_ + 2 * c0;
        }

        // record = 16B; strides: g:512B, kt:4096B, cb:36864B
        const char* wfb = (const char*)g_wf
            + ((size_t)(fb * 32) * NORD * 8 + wn * 4) * 512 + lane * 16;

        // init accumulators with the exact P0 bias (sum of 16 partials)
        float acc[2][8][4];
        #pragma unroll
        for (int j = 0; j < 8; j++) {
            const int fz = f0 + wn * 64 + j * 8 + tig * 2;
            float2 bz = make_float2(0.f, 0.f);
            #pragma unroll
            for (int p = 0; p < 16; p++) {
                float2 v = *(const float2*)&g_bias_part[p][fz];
                bz.x += v.x;
                bz.y += v.y;
            }
            #pragma unroll
            for (int mt = 0; mt < 2; mt++) {
                acc[mt][j][0] = bz.x; acc[mt][j][1] = bz.y;
                acc[mt][j][2] = bz.x; acc[mt][j][3] = bz.y;
            }
        }

        float2 dv[8];
        #pragma unroll
        for (int q = 0; q < 4; q++) {
            dv[q * 2 + 0] = *(const float2*)(dp[q]);
            dv[q * 2 + 1] = *(const float2*)(dp[q] + 8);
        }

        for (int cb = 0; cb < 32; cb++) {
            float t[16], pa[16], pb[16];
            #pragma unroll
            for (int q = 0; q < 4; q++) {
                t[q * 4 + 0] = fmaf(dv[q * 2 + 0].x, scale, tc);
                t[q * 4 + 1] = fmaf(dv[q * 2 + 0].y, scale, tc);
                t[q * 4 + 2] = fmaf(dv[q * 2 + 1].x, scale, tc);
                t[q * 4 + 3] = fmaf(dv[q * 2 + 1].y, scale, tc);
            }
            if (cb < 31) {
                #pragma unroll
                for (int q = 0; q < 4; q++) {
                    dv[q * 2 + 0] = *(const float2*)(dp[q] + (cb + 1) * 16);
                    dv[q * 2 + 1] = *(const float2*)(dp[q] + (cb + 1) * 16 + 8);
                }
            }
            #pragma unroll
            for (int i = 0; i < 16; i++) { pa[i] = 1.0f; pb[i] = t[i]; }

            const char* wpc = wfb + (size_t)cb * (NORD * 8 * 512);

            #pragma unroll
            for (int kt = 1; kt < NORD; kt++) {
                const char* wpt = wpc + (size_t)kt * 4096;
                uint4 b[4];
                #pragma unroll
                for (int g = 0; g < 4; g++)
                    b[g] = *(const uint4*)(wpt + g * 512);

                uint32_t ah[2][4];
                if (kt >= 2) {
                    const float an = (2.0f * kt - 1.0f) / (float)kt;
                    const float bn = (float)(kt - 1) / (float)kt;
                    #pragma unroll
                    for (int i = 0; i < 16; i++) {
                        float p2 = an * t[i] * pb[i] - bn * pa[i];
                        pa[i] = pb[i];
                        pb[i] = p2;
                    }
                }
                #pragma unroll
                for (int mt = 0; mt < 2; mt++) {
                    ah[mt][0] = pack_h(pb[IDX(mt,0,0)], pb[IDX(mt,0,1)]);
                    ah[mt][1] = pack_h(pb[IDX(mt,1,0)], pb[IDX(mt,1,1)]);
                    ah[mt][2] = pack_h(pb[IDX(mt,0,2)], pb[IDX(mt,0,3)]);
                    ah[mt][3] = pack_h(pb[IDX(mt,1,2)], pb[IDX(mt,1,3)]);
                }

                #pragma unroll
                for (int g = 0; g < 4; g++)
                    #pragma unroll
                    for (int mt = 0; mt < 2; mt++) {
                        mma_fp16(acc[mt][g * 2 + 0], ah[mt], b[g].x, b[g].y);
                        mma_fp16(acc[mt][g * 2 + 1], ah[mt], b[g].z, b[g].w);
                    }
            }
        }

        // epilogue
        const int g = lr;
        #pragma unroll
        for (int mt = 0; mt < 2; mt++) {
            const int mb = m0 + wm * 32 + mt * 16;
            #pragma unroll
            for (int j = 0; j < 8; j++) {
                const int f = f0 + wn * 64 + j * 8 + tig * 2;
                float2 lo = make_float2(acc[mt][j][0], acc[mt][j][1]);
                float2 hi = make_float2(acc[mt][j][2], acc[mt][j][3]);
                *(float2*)(out + (size_t)(mb + g)     * F_ + f) = lo;
                *(float2*)(out + (size_t)(mb + g + 8) * F_ + f) = hi;
            }
        }
    }

    // zero g_x2 for the next launch (reads finished in phase 1; device
    // globals start zeroed, and every completed launch re-zeroes here)
    if (bx < 32) g_x2[bx * 256 + tid] = 0.0f;
}

// ---------------- launch ---------------------------------------------------
extern "C" void kernel_launch(void* const* d_in, const int* in_sizes, int n_in,
                              void* d_out, int out_size) {
    const float* x   = (const float*)d_in[0];   // [8192,256]
    const float* cen = (const float*)d_in[1];   // [512,256]
    const float* w   = (const float*)d_in[2];   // [512,9,256]
    float* out = (float*)d_out;                 // [8192,256]

    k_prep_all<<<NB_ALL, 256>>>(x, cen, w);
    k_main<<<GRID_MAIN, 256>>>(out);
}